// round 8
// baseline (speedup 1.0000x reference)
#include <cuda_runtime.h>
#include <math.h>

#define SEQ   4096
#define HIDI  2880
#define NH    64
#define NKV   8
#define DH    64
#define QKV_N 5120          // (64 + 2*8) * 64
#define ATT_N 4096          // 64 * 64

// Scratch (allocation-free rule: __device__ globals)
__device__ float g_qkv[(size_t)SEQ * QKV_N];   // [S, 5120]  q|k|v per row
__device__ float g_attn[(size_t)SEQ * ATT_N];  // [S, 4096]  attention output

// ---------------------------------------------------------------------------
// GEMM: C[M,N] = A[M,K] @ W[K,N] + bias[N]
// BM=128, BN=64, BK=8, 256 threads. Inner loop uses packed fma.rn.f32x2
// (sm_100+ family feature -- NOT an 'a'-suffix-gated instruction).
// Requires: M%128==0, N%64==0, K%8==0 (all satisfied here).
// ---------------------------------------------------------------------------
__global__ __launch_bounds__(256) void sgemm_bias(
    const float* __restrict__ A, const float* __restrict__ W,
    const float* __restrict__ bias, float* __restrict__ C,
    int M, int N, int K)
{
    __shared__ float As[8][132];   // padded: stride 132 -> conflict-free stores
    __shared__ float Bs[8][64];

    const int tid = threadIdx.x;
    const int ty  = tid >> 4;        // 0..15  (8 rows each)
    const int tx  = tid & 15;        // 0..15  (4 cols each)
    const int row0 = blockIdx.y * 128;
    const int col0 = blockIdx.x * 64;

    const int ar = tid >> 1;         // 0..127 : A row within tile
    const int ac = (tid & 1) * 4;    // 0 or 4 : A k-offset (float4)
    const int br = tid >> 4;         // 0..7   : B k-row (tid<128 only)
    const int bc = (tid & 15) * 4;   // 0..60  : B col (float4)

    unsigned long long acc[4][4];    // packed f32x2 accumulators (rows 2i,2i+1)
    #pragma unroll
    for (int i = 0; i < 4; i++)
        #pragma unroll
        for (int j = 0; j < 4; j++) acc[i][j] = 0ULL;

    const float* Aptr = A + (size_t)(row0 + ar) * K + ac;
    const float* Wptr = W + (size_t)br * N + col0 + bc;

    for (int k0 = 0; k0 < K; k0 += 8) {
        float4 av = *reinterpret_cast<const float4*>(Aptr + k0);
        As[ac + 0][ar] = av.x;
        As[ac + 1][ar] = av.y;
        As[ac + 2][ar] = av.z;
        As[ac + 3][ar] = av.w;
        if (tid < 128) {
            float4 bv = *reinterpret_cast<const float4*>(Wptr + (size_t)k0 * N);
            *reinterpret_cast<float4*>(&Bs[br][bc]) = bv;
        }
        __syncthreads();

        #pragma unroll
        for (int kk = 0; kk < 8; kk++) {
            // 4 packed row-pairs of A, straight from shared (already adjacent)
            const unsigned long long* ap =
                reinterpret_cast<const unsigned long long*>(&As[kk][ty * 8]);
            unsigned long long aa0 = ap[0], aa1 = ap[1], aa2 = ap[2], aa3 = ap[3];
            float4 b = *reinterpret_cast<const float4*>(&Bs[kk][tx * 4]);
            unsigned long long bd0, bd1, bd2, bd3;
            asm("mov.b64 %0, {%1, %1};" : "=l"(bd0) : "f"(b.x));
            asm("mov.b64 %0, {%1, %1};" : "=l"(bd1) : "f"(b.y));
            asm("mov.b64 %0, {%1, %1};" : "=l"(bd2) : "f"(b.z));
            asm("mov.b64 %0, {%1, %1};" : "=l"(bd3) : "f"(b.w));
            unsigned long long aa[4] = {aa0, aa1, aa2, aa3};
            unsigned long long bb[4] = {bd0, bd1, bd2, bd3};
            #pragma unroll
            for (int i = 0; i < 4; i++)
                #pragma unroll
                for (int j = 0; j < 4; j++)
                    asm("fma.rn.f32x2 %0, %1, %2, %0;"
                        : "+l"(acc[i][j]) : "l"(aa[i]), "l"(bb[j]));
        }
        __syncthreads();
    }

    #pragma unroll
    for (int i = 0; i < 4; i++) {
        const int r0 = row0 + ty * 8 + 2 * i;
        #pragma unroll
        for (int j = 0; j < 4; j++) {
            const int c = col0 + tx * 4 + j;
            float2 v = *reinterpret_cast<float2*>(&acc[i][j]);
            float bsv = bias[c];
            C[(size_t)r0 * N + c]       = v.x + bsv;
            C[(size_t)(r0 + 1) * N + c] = v.y + bsv;
        }
    }
}

// ---------------------------------------------------------------------------
// YaRN RoPE, in place on g_qkv. One warp per (token, head-row); head rows
// 0..63 = q heads (also applies D^-0.5), 64..71 = k heads. Offset within a
// qkv row is h*64 for BOTH cases (k region starts exactly at 4096).
// ---------------------------------------------------------------------------
__global__ void rope_kernel(float* __restrict__ qkv, const int* __restrict__ pos)
{
    const int h = blockIdx.y * blockDim.y + threadIdx.y;  // 0..71
    if (h >= NH + NKV) return;
    const int t = blockIdx.x;
    const int i = threadIdx.x;                            // 0..31 freq index

    // inv_freq (YaRN): pf = 150000^(i/32); low=8, high=18 (precomputed exactly)
    const double LN_BASE = 11.918390573078392;            // ln(150000)
    double pf = exp((double)i * (LN_BASE / 32.0));
    double extrap = 1.0 / pf;
    double interp = extrap * (1.0 / 32.0);
    double ramp = ((double)i - 8.0) * 0.1;                // (i-low)/(high-low)
    ramp = fmin(fmax(ramp, 0.0), 1.0);
    float invf = (float)(interp * ramp + extrap * (1.0 - ramp));

    float fr = (float)pos[t] * invf;
    float s, c;
    sincosf(fr, &s, &c);
    const float mscale = 1.3465735902799727f;             // 0.1*ln(32)+1
    c *= mscale; s *= mscale;

    const float scale = (h < NH) ? 0.125f : 1.0f;         // D^-0.5 for q only
    float* base = qkv + (size_t)t * QKV_N + h * 64;
    float x1 = base[i];
    float x2 = base[i + 32];
    base[i]      = (x1 * c - x2 * s) * scale;
    base[i + 32] = (x2 * c + x1 * s) * scale;
}

// ---------------------------------------------------------------------------
// Sliding-window attention with sinks.
// Block = (kv-head kk, token p) -- kk fastest so the 8 CTAs sharing one
// token's K/V window are adjacent in launch order (L2 reuse).
// 256 threads = 8 warps; warp g handles q-head g of the group. Keys are the
// last min(p+1,128) positions. K tile staged in smem (stride 68:
// conflict-free for float4 score reads AND PV lane reads), then the SAME
// buffer is reloaded with V after a sync (keeps smem < 48KB).
// ---------------------------------------------------------------------------
__global__ __launch_bounds__(256) void attn_kernel(
    const float* __restrict__ qkv, const float* __restrict__ sinks,
    float* __restrict__ out)
{
    __shared__ float KV[128 * 68];
    __shared__ float qs[8 * 64];
    __shared__ float sc[8 * 128];

    const int p    = blockIdx.y;
    const int kk   = blockIdx.x;
    const int tid  = threadIdx.x;
    const int lane = tid & 31;
    const int w    = tid >> 5;           // warp id == group head g
    const int L    = min(p + 1, 128);
    const int ks   = p + 1 - L;

    // ---- load K window (128x64 max) ----
    const float* kbase = qkv + (size_t)ks * QKV_N + ATT_N + kk * 64;
    for (int idx = tid; idx < 128 * 16; idx += 256) {
        int j = idx >> 4, f = idx & 15;
        if (j < L)
            *reinterpret_cast<float4*>(&KV[j * 68 + f * 4]) =
                *reinterpret_cast<const float4*>(kbase + (size_t)j * QKV_N + f * 4);
    }
    // ---- load q for the 8 heads of this group ----
    if (tid < 128) {
        int g = tid >> 4, f = tid & 15;
        *reinterpret_cast<float4*>(&qs[g * 64 + f * 4]) =
            *reinterpret_cast<const float4*>(
                qkv + (size_t)p * QKV_N + (kk * 8 + g) * 64 + f * 4);
    }
    __syncthreads();

    // ---- scores (each lane: keys lane, lane+32, lane+64, lane+96) ----
    float sv[4];
    {
        const float4* qv = reinterpret_cast<const float4*>(qs + w * 64);
        #pragma unroll
        for (int jj = 0; jj < 4; jj++) {
            int j = lane + jj * 32;
            float s = -3.0e38f;
            if (j < L) {
                const float4* kv = reinterpret_cast<const float4*>(KV + j * 68);
                float a = 0.f;
                #pragma unroll
                for (int f = 0; f < 16; f++) {
                    float4 kq = kv[f];
                    float4 qq = qv[f];
                    a += kq.x * qq.x + kq.y * qq.y + kq.z * qq.z + kq.w * qq.w;
                }
                s = a;
            }
            sv[jj] = s;
        }
    }

    // ---- softmax with sink (register/warp-local) ----
    const float sink = sinks[kk * 8 + w];
    float m = fmaxf(fmaxf(sv[0], sv[1]), fmaxf(sv[2], sv[3]));
    #pragma unroll
    for (int o = 16; o > 0; o >>= 1) m = fmaxf(m, __shfl_xor_sync(0xffffffffu, m, o));
    m = fmaxf(m, sink);
    float sum = 0.f;
    #pragma unroll
    for (int jj = 0; jj < 4; jj++) {
        float e = expf(sv[jj] - m);      // invalid slots: exp(-huge) = 0
        sum += e;
        sc[w * 128 + lane + jj * 32] = e;
    }
    #pragma unroll
    for (int o = 16; o > 0; o >>= 1) sum += __shfl_xor_sync(0xffffffffu, sum, o);
    const float inv_d = 1.0f / (sum + expf(sink - m));

    __syncthreads();                     // all warps done with K

    // ---- reload buffer with V ----
    const float* vbase = qkv + (size_t)ks * QKV_N + ATT_N + NKV * 64 + kk * 64;
    for (int idx = tid; idx < 128 * 16; idx += 256) {
        int j = idx >> 4, f = idx & 15;
        if (j < L)
            *reinterpret_cast<float4*>(&KV[j * 68 + f * 4]) =
                *reinterpret_cast<const float4*>(vbase + (size_t)j * QKV_N + f * 4);
    }
    __syncthreads();

    // ---- P @ V : warp g, lane handles dims lane and lane+32 ----
    float acc0 = 0.f, acc1 = 0.f;
    for (int j = 0; j < L; j++) {
        float pw = sc[w * 128 + j];
        acc0 += pw * KV[j * 68 + lane];
        acc1 += pw * KV[j * 68 + 32 + lane];
    }
    const size_t o = (size_t)p * ATT_N + (kk * 8 + w) * 64 + lane;
    out[o]      = acc0 * inv_d;
    out[o + 32] = acc1 * inv_d;
}

// ---------------------------------------------------------------------------
extern "C" void kernel_launch(void* const* d_in, const int* in_sizes, int n_in,
                              void* d_out, int out_size)
{
    const float* hidden = (const float*)d_in[0];
    const int*   pos    = (const int*)  d_in[1];
    const float* w_qkv  = (const float*)d_in[2];
    const float* b_qkv  = (const float*)d_in[3];
    const float* w_o    = (const float*)d_in[4];
    const float* b_o    = (const float*)d_in[5];
    const float* sinks  = (const float*)d_in[6];
    float* outp = (float*)d_out;

    void* qkv_p;  cudaGetSymbolAddress(&qkv_p,  g_qkv);
    void* attn_p; cudaGetSymbolAddress(&attn_p, g_attn);
    float* qkvb  = (float*)qkv_p;
    float* attnb = (float*)attn_p;

    // 1) QKV projection: [4096,2880] @ [2880,5120] + bias
    sgemm_bias<<<dim3(QKV_N / 64, SEQ / 128), 256>>>(
        hidden, w_qkv, b_qkv, qkvb, SEQ, QKV_N, HIDI);

    // 2) YaRN RoPE in place (q scaled by D^-0.5)
    rope_kernel<<<dim3(SEQ, 9), dim3(32, 8)>>>(qkvb, pos);

    // 3) Sliding-window attention with sinks
    attn_kernel<<<dim3(NKV, SEQ), 256>>>(qkvb, sinks, attnb);

    // 4) Output projection: [4096,4096] @ [4096,2880] + bias
    sgemm_bias<<<dim3(HIDI / 64, SEQ / 128), 256>>>(
        attnb, w_o, b_o, outp, SEQ, HIDI, ATT_N);
}

// round 9
// speedup vs baseline: 1.7973x; 1.7973x over previous
#include <cuda_runtime.h>
#include <cuda_bf16.h>
#include <math.h>
#include <stdint.h>

#define SEQ   4096
#define HIDI  2880
#define NH    64
#define NKV   8
#define DH    64
#define QKV_N 5120          // (64 + 2*8) * 64
#define ATT_N 4096          // 64 * 64

// ---------------------------------------------------------------------------
// Scratch (allocation-free rule: __device__ globals)
// ---------------------------------------------------------------------------
__device__ float g_qkv [(size_t)SEQ * QKV_N];          // [S,5120] q|k|v rows
__device__ __nv_bfloat16 g_a1h[(size_t)SEQ * HIDI];    // hidden split
__device__ __nv_bfloat16 g_a1l[(size_t)SEQ * HIDI];
__device__ __nv_bfloat16 g_w1h[(size_t)QKV_N * HIDI];  // w_qkv^T split [N,K]
__device__ __nv_bfloat16 g_w1l[(size_t)QKV_N * HIDI];
__device__ __nv_bfloat16 g_a2h[(size_t)SEQ * ATT_N];   // attn-out split (fused)
__device__ __nv_bfloat16 g_a2l[(size_t)SEQ * ATT_N];
__device__ __nv_bfloat16 g_w2h[(size_t)HIDI * ATT_N];  // w_o^T split [N,K]
__device__ __nv_bfloat16 g_w2l[(size_t)HIDI * ATT_N];

// ---------------------------------------------------------------------------
// Portable (non-suffix-gated) PTX helpers: cp.async / ldmatrix / mma.sync
// ---------------------------------------------------------------------------
__device__ __forceinline__ uint32_t smem_to_u32(const void* p) {
    uint32_t a;
    asm("{ .reg .u64 t; cvta.to.shared.u64 t, %1; cvt.u32.u64 %0, t; }"
        : "=r"(a) : "l"(p));
    return a;
}
__device__ __forceinline__ void cp16(uint32_t saddr, const void* g) {
    asm volatile("cp.async.cg.shared.global [%0], [%1], 16;"
                 :: "r"(saddr), "l"(g) : "memory");
}
#define CP_COMMIT() asm volatile("cp.async.commit_group;" ::: "memory")
#define CP_WAIT0()  asm volatile("cp.async.wait_group 0;" ::: "memory")

#define LDSM4(r0, r1, r2, r3, addr) \
    asm volatile("ldmatrix.sync.aligned.m8n8.x4.shared.b16 {%0,%1,%2,%3}, [%4];" \
        : "=r"(r0), "=r"(r1), "=r"(r2), "=r"(r3) : "r"(addr))

#define MMA_BF16(d, a, b) \
    asm volatile("mma.sync.aligned.m16n8k16.row.col.f32.bf16.bf16.f32 " \
        "{%0,%1,%2,%3}, {%4,%5,%6,%7}, {%8,%9}, {%0,%1,%2,%3};" \
        : "+f"((d)[0]), "+f"((d)[1]), "+f"((d)[2]), "+f"((d)[3]) \
        : "r"((a)[0]), "r"((a)[1]), "r"((a)[2]), "r"((a)[3]), \
          "r"((b)[0]), "r"((b)[1]))

// ---------------------------------------------------------------------------
// Elementwise split (vectorized): x -> bf16 hi + bf16 lo (lo = bf16(x - hi))
// ---------------------------------------------------------------------------
__global__ void split_rows(const float4* __restrict__ X,
                           __nv_bfloat162* __restrict__ hi,
                           __nv_bfloat162* __restrict__ lo, size_t n4)
{
    for (size_t i = (size_t)blockIdx.x * blockDim.x + threadIdx.x; i < n4;
         i += (size_t)gridDim.x * blockDim.x) {
        float4 v = X[i];
        __nv_bfloat16 hx = __float2bfloat16(v.x);
        __nv_bfloat16 hy = __float2bfloat16(v.y);
        __nv_bfloat16 hz = __float2bfloat16(v.z);
        __nv_bfloat16 hw = __float2bfloat16(v.w);
        hi[2 * i]     = __nv_bfloat162(hx, hy);
        hi[2 * i + 1] = __nv_bfloat162(hz, hw);
        lo[2 * i]     = __nv_bfloat162(
            __float2bfloat16(v.x - __bfloat162float(hx)),
            __float2bfloat16(v.y - __bfloat162float(hy)));
        lo[2 * i + 1] = __nv_bfloat162(
            __float2bfloat16(v.z - __bfloat162float(hz)),
            __float2bfloat16(v.w - __bfloat162float(hw)));
    }
}

// ---------------------------------------------------------------------------
// Transpose + split: W[K,N] (row-major) -> T[N,K] bf16 hi/lo
// ---------------------------------------------------------------------------
__global__ void transpose_split(const float* __restrict__ W,
                                __nv_bfloat16* __restrict__ Thi,
                                __nv_bfloat16* __restrict__ Tlo, int K, int N)
{
    __shared__ float t[32][33];
    const int n0 = blockIdx.x * 32, k0 = blockIdx.y * 32;
    const int tx = threadIdx.x, ty = threadIdx.y;     // 32 x 8
    #pragma unroll
    for (int i = 0; i < 32; i += 8)
        t[ty + i][tx] = W[(size_t)(k0 + ty + i) * N + n0 + tx];
    __syncthreads();
    #pragma unroll
    for (int i = 0; i < 32; i += 8) {
        float v = t[tx][ty + i];                      // = W[k0+tx][n0+ty+i]
        __nv_bfloat16 h = __float2bfloat16(v);
        size_t o = (size_t)(n0 + ty + i) * K + k0 + tx;
        Thi[o] = h;
        Tlo[o] = __float2bfloat16(v - __bfloat162float(h));
    }
}

// ---------------------------------------------------------------------------
// Stage loader: copy one BK=32 chunk of Ah/Al (128 rows) and Bh/Bl (BN rows)
// into a shared stage. Rows padded to 80B (40 bf16) -> ldmatrix conflict-free
// (80*i mod 128 covers 8 distinct 16B chunks).
// Stage layout: Ah | Al | Bh | Bl  (ABY=128*80, BBY=BN*80 bytes)
// ---------------------------------------------------------------------------
template <int BN>
__device__ __forceinline__ void stage_load(
    uint32_t st,
    const __nv_bfloat16* __restrict__ Ah, const __nv_bfloat16* __restrict__ Al,
    const __nv_bfloat16* __restrict__ Bh, const __nv_bfloat16* __restrict__ Bl,
    int row0, int col0, int K, int k0, int tid)
{
    constexpr int ABY = 128 * 80;
    constexpr int BBY = BN * 80;
    #pragma unroll
    for (int i = tid; i < 512; i += 256) {            // A: 128 rows x 4 chunks
        int r = i >> 2, c = i & 3;
        size_t go = (size_t)(row0 + r) * K + k0 + c * 8;
        uint32_t so = r * 80 + c * 16;
        cp16(st + so,       Ah + go);
        cp16(st + ABY + so, Al + go);
    }
    #pragma unroll
    for (int i = tid; i < BN * 4; i += 256) {         // B: BN rows x 4 chunks
        int r = i >> 2, c = i & 3;
        size_t go = (size_t)(col0 + r) * K + k0 + c * 8;
        uint32_t so = r * 80 + c * 16;
        cp16(st + 2 * ABY + so,       Bh + go);
        cp16(st + 2 * ABY + BBY + so, Bl + go);
    }
    CP_COMMIT();
}

// ---------------------------------------------------------------------------
// Split-bf16 GEMM via mma.sync.m16n8k16 (portable sm_80+ path; tcgen05 is
// suffix-gated and unavailable under the harness's sm_103 PTX target).
// C[M,N] = A[M,K] @ B^T + bias, B stored [N,K] K-major.
// Products: Ah*Bh + Ah*Bl + Al*Bh, fp32 accum (dropped Al*Bl ~2^-18 rel).
// Block 256 thr = 8 warps (4 along M x 2 along N); BM=128, BN=128|96, BK=32.
// cp.async double-buffered: iter ch+1 writes stage ch&1 only after the
// top-of-loop barrier every warp reaches post-compute(ch) -> 1 sync/iter.
// ---------------------------------------------------------------------------
template <int BN>
__global__ __launch_bounds__(256, 1) void gemm_mma(
    const __nv_bfloat16* __restrict__ Ah, const __nv_bfloat16* __restrict__ Al,
    const __nv_bfloat16* __restrict__ Bh, const __nv_bfloat16* __restrict__ Bl,
    const float* __restrict__ bias, float* __restrict__ C,
    int M, int N, int K)
{
    extern __shared__ char smem[];
    constexpr int ABY   = 128 * 80;
    constexpr int BBY   = BN * 80;
    constexpr int STAGE = 2 * ABY + 2 * BBY;
    constexpr int WN    = BN / 2;                     // warp N extent
    constexpr int NT    = WN / 8;                     // n-tiles per warp

    const int tid = threadIdx.x, lane = tid & 31, wid = tid >> 5;
    const int wm = wid & 3, wn = wid >> 2;            // 4 x 2 warp grid
    const int row0 = blockIdx.y * 128, col0 = blockIdx.x * BN;
    const uint32_t sb = smem_to_u32(smem);

    float acc[2][NT][4];
    #pragma unroll
    for (int mi = 0; mi < 2; mi++)
        #pragma unroll
        for (int ni = 0; ni < NT; ni++)
            #pragma unroll
            for (int k = 0; k < 4; k++) acc[mi][ni][k] = 0.f;

    // per-lane ldmatrix address components
    // A x4: lanes 0-15 -> rows 0-15 (m0,m1), lanes 16-31 -> same rows +16B (k+8)
    const int rA  = lane & 15;
    const int cAb = (lane >> 4) * 16;
    // B x4: lanes 0-7 n-rows 0-7 @k0 | 8-15 same rows +16B | 16-23 n-rows 8-15 | 24-31 +16B
    const int rB  = (lane & 7) + ((lane >> 4) << 3);
    const int cBb = ((lane >> 3) & 1) * 16;

    const int nch = K / 32;
    stage_load<BN>(sb, Ah, Al, Bh, Bl, row0, col0, K, 0, tid);

    for (int ch = 0; ch < nch; ++ch) {
        CP_WAIT0();
        __syncthreads();
        if (ch + 1 < nch)
            stage_load<BN>(sb + ((ch + 1) & 1) * STAGE,
                           Ah, Al, Bh, Bl, row0, col0, K, (ch + 1) * 32, tid);
        const uint32_t st = sb + (ch & 1) * STAGE;

        #pragma unroll
        for (int ks = 0; ks < 2; ks++) {
            uint32_t ah[2][4], al[2][4], bh[NT][2], bl[NT][2];
            #pragma unroll
            for (int mi = 0; mi < 2; mi++) {
                uint32_t a = st + (wm * 32 + mi * 16 + rA) * 80 + ks * 32 + cAb;
                LDSM4(ah[mi][0], ah[mi][1], ah[mi][2], ah[mi][3], a);
                LDSM4(al[mi][0], al[mi][1], al[mi][2], al[mi][3], a + ABY);
            }
            #pragma unroll
            for (int j = 0; j < NT / 2; j++) {        // each x4 = 2 n-tiles
                uint32_t a = st + 2 * ABY + (wn * WN + j * 16 + rB) * 80
                           + ks * 32 + cBb;
                LDSM4(bh[2*j][0], bh[2*j][1], bh[2*j+1][0], bh[2*j+1][1], a);
                LDSM4(bl[2*j][0], bl[2*j][1], bl[2*j+1][0], bl[2*j+1][1], a + BBY);
            }
            #pragma unroll
            for (int ni = 0; ni < NT; ni++)
                #pragma unroll
                for (int mi = 0; mi < 2; mi++) {
                    MMA_BF16(acc[mi][ni], ah[mi], bh[ni]);
                    MMA_BF16(acc[mi][ni], ah[mi], bl[ni]);
                    MMA_BF16(acc[mi][ni], al[mi], bh[ni]);
                }
        }
    }

    // epilogue: c0,c1 = (row lane/4, col 2(lane%4)+{0,1}); c2,c3 = row+8
    const int rb = row0 + wm * 32 + (lane >> 2);
    const int cb = col0 + wn * WN + (lane & 3) * 2;
    #pragma unroll
    for (int mi = 0; mi < 2; mi++)
        #pragma unroll
        for (int ni = 0; ni < NT; ni++) {
            int c = cb + ni * 8;
            float2 bz = *reinterpret_cast<const float2*>(bias + c);
            int r = rb + mi * 16;
            float2 v0 = make_float2(acc[mi][ni][0] + bz.x, acc[mi][ni][1] + bz.y);
            float2 v1 = make_float2(acc[mi][ni][2] + bz.x, acc[mi][ni][3] + bz.y);
            *reinterpret_cast<float2*>(C + (size_t)r * N + c)       = v0;
            *reinterpret_cast<float2*>(C + (size_t)(r + 8) * N + c) = v1;
        }
}

// ---------------------------------------------------------------------------
// YaRN RoPE, in place on g_qkv. One warp per (token, head-row); head rows
// 0..63 = q heads (also applies D^-0.5), 64..71 = k heads.
// ---------------------------------------------------------------------------
__global__ void rope_kernel(float* __restrict__ qkv, const int* __restrict__ pos)
{
    const int h = blockIdx.y * blockDim.y + threadIdx.y;  // 0..71
    if (h >= NH + NKV) return;
    const int t = blockIdx.x;
    const int i = threadIdx.x;                            // 0..31 freq index

    const double LN_BASE = 11.918390573078392;            // ln(150000)
    double pf = exp((double)i * (LN_BASE / 32.0));
    double extrap = 1.0 / pf;
    double interp = extrap * (1.0 / 32.0);
    double ramp = ((double)i - 8.0) * 0.1;                // low=8, high=18
    ramp = fmin(fmax(ramp, 0.0), 1.0);
    float invf = (float)(interp * ramp + extrap * (1.0 - ramp));

    float fr = (float)pos[t] * invf;
    float s, c;
    sincosf(fr, &s, &c);
    const float mscale = 1.3465735902799727f;             // 0.1*ln(32)+1
    c *= mscale; s *= mscale;

    const float scale = (h < NH) ? 0.125f : 1.0f;         // D^-0.5 for q only
    float* base = qkv + (size_t)t * QKV_N + h * 64;
    float x1 = base[i];
    float x2 = base[i + 32];
    base[i]      = (x1 * c - x2 * s) * scale;
    base[i + 32] = (x2 * c + x1 * s) * scale;
}

// ---------------------------------------------------------------------------
// Sliding-window attention with sinks (fp32). Block = (kv-head, token).
// Warp g handles q-head g of the group; last min(p+1,128) keys. Epilogue
// writes the bf16 hi/lo SPLIT of the output (fused O-GEMM input prep).
// ---------------------------------------------------------------------------
__global__ __launch_bounds__(256) void attn_kernel(
    const float* __restrict__ qkv, const float* __restrict__ sinks,
    __nv_bfloat16* __restrict__ oh, __nv_bfloat16* __restrict__ ol)
{
    __shared__ float KV[128 * 68];
    __shared__ float qs[8 * 64];
    __shared__ float sc[8 * 128];

    const int p    = blockIdx.y;
    const int kk   = blockIdx.x;
    const int tid  = threadIdx.x;
    const int lane = tid & 31;
    const int w    = tid >> 5;
    const int L    = min(p + 1, 128);
    const int ks   = p + 1 - L;

    const float* kbase = qkv + (size_t)ks * QKV_N + ATT_N + kk * 64;
    for (int idx = tid; idx < 128 * 16; idx += 256) {
        int j = idx >> 4, f = idx & 15;
        if (j < L)
            *reinterpret_cast<float4*>(&KV[j * 68 + f * 4]) =
                *reinterpret_cast<const float4*>(kbase + (size_t)j * QKV_N + f * 4);
    }
    if (tid < 128) {
        int g = tid >> 4, f = tid & 15;
        *reinterpret_cast<float4*>(&qs[g * 64 + f * 4]) =
            *reinterpret_cast<const float4*>(
                qkv + (size_t)p * QKV_N + (kk * 8 + g) * 64 + f * 4);
    }
    __syncthreads();

    float sv[4];
    {
        const float4* qv = reinterpret_cast<const float4*>(qs + w * 64);
        #pragma unroll
        for (int jj = 0; jj < 4; jj++) {
            int j = lane + jj * 32;
            float s = -3.0e38f;
            if (j < L) {
                const float4* kv = reinterpret_cast<const float4*>(KV + j * 68);
                float a = 0.f;
                #pragma unroll
                for (int f = 0; f < 16; f++) {
                    float4 kq = kv[f];
                    float4 qq = qv[f];
                    a += kq.x * qq.x + kq.y * qq.y + kq.z * qq.z + kq.w * qq.w;
                }
                s = a;
            }
            sv[jj] = s;
        }
    }

    const float sink = sinks[kk * 8 + w];
    float m = fmaxf(fmaxf(sv[0], sv[1]), fmaxf(sv[2], sv[3]));
    #pragma unroll
    for (int o = 16; o > 0; o >>= 1) m = fmaxf(m, __shfl_xor_sync(0xffffffffu, m, o));
    m = fmaxf(m, sink);
    float sum = 0.f;
    #pragma unroll
    for (int jj = 0; jj < 4; jj++) {
        float e = expf(sv[jj] - m);      // invalid slots: exp(-huge) = 0
        sum += e;
        sc[w * 128 + lane + jj * 32] = e;
    }
    #pragma unroll
    for (int o = 16; o > 0; o >>= 1) sum += __shfl_xor_sync(0xffffffffu, sum, o);
    const float inv_d = 1.0f / (sum + expf(sink - m));

    __syncthreads();

    const float* vbase = qkv + (size_t)ks * QKV_N + ATT_N + NKV * 64 + kk * 64;
    for (int idx = tid; idx < 128 * 16; idx += 256) {
        int j = idx >> 4, f = idx & 15;
        if (j < L)
            *reinterpret_cast<float4*>(&KV[j * 68 + f * 4]) =
                *reinterpret_cast<const float4*>(vbase + (size_t)j * QKV_N + f * 4);
    }
    __syncthreads();

    float acc0 = 0.f, acc1 = 0.f;
    for (int j = 0; j < L; j++) {
        float pw = sc[w * 128 + j];
        acc0 += pw * KV[j * 68 + lane];
        acc1 += pw * KV[j * 68 + 32 + lane];
    }
    const size_t o = (size_t)p * ATT_N + (kk * 8 + w) * 64 + lane;
    float v0 = acc0 * inv_d;
    float v1 = acc1 * inv_d;
    __nv_bfloat16 h0 = __float2bfloat16(v0);
    __nv_bfloat16 h1 = __float2bfloat16(v1);
    oh[o]      = h0;
    oh[o + 32] = h1;
    ol[o]      = __float2bfloat16(v0 - __bfloat162float(h0));
    ol[o + 32] = __float2bfloat16(v1 - __bfloat162float(h1));
}

// ---------------------------------------------------------------------------
extern "C" void kernel_launch(void* const* d_in, const int* in_sizes, int n_in,
                              void* d_out, int out_size)
{
    const float* hidden = (const float*)d_in[0];
    const int*   pos    = (const int*)  d_in[1];
    const float* w_qkv  = (const float*)d_in[2];
    const float* b_qkv  = (const float*)d_in[3];
    const float* w_o    = (const float*)d_in[4];
    const float* b_o    = (const float*)d_in[5];
    const float* sinks  = (const float*)d_in[6];
    float* outp = (float*)d_out;

    void* p;
    cudaGetSymbolAddress(&p, g_qkv);  float* qkvb  = (float*)p;
    cudaGetSymbolAddress(&p, g_a1h);  __nv_bfloat16* a1h = (__nv_bfloat16*)p;
    cudaGetSymbolAddress(&p, g_a1l);  __nv_bfloat16* a1l = (__nv_bfloat16*)p;
    cudaGetSymbolAddress(&p, g_w1h);  __nv_bfloat16* w1h = (__nv_bfloat16*)p;
    cudaGetSymbolAddress(&p, g_w1l);  __nv_bfloat16* w1l = (__nv_bfloat16*)p;
    cudaGetSymbolAddress(&p, g_a2h);  __nv_bfloat16* a2h = (__nv_bfloat16*)p;
    cudaGetSymbolAddress(&p, g_a2l);  __nv_bfloat16* a2l = (__nv_bfloat16*)p;
    cudaGetSymbolAddress(&p, g_w2h);  __nv_bfloat16* w2h = (__nv_bfloat16*)p;
    cudaGetSymbolAddress(&p, g_w2l);  __nv_bfloat16* w2l = (__nv_bfloat16*)p;

    // dynamic smem: 2 stages x (2*128*80 + 2*BN*80)
    constexpr int SMEM1 = 2 * (2 * 128 * 80 + 2 * 128 * 80);  // 81920 (BN=128)
    constexpr int SMEM2 = 2 * (2 * 128 * 80 + 2 * 96 * 80);   // 71680 (BN=96)
    cudaFuncSetAttribute(gemm_mma<128>,
                         cudaFuncAttributeMaxDynamicSharedMemorySize, SMEM1);
    cudaFuncSetAttribute(gemm_mma<96>,
                         cudaFuncAttributeMaxDynamicSharedMemorySize, SMEM2);

    // 1) split inputs of QKV GEMM
    split_rows<<<2048, 256>>>((const float4*)hidden, (__nv_bfloat162*)a1h,
                              (__nv_bfloat162*)a1l, (size_t)SEQ * HIDI / 4);
    transpose_split<<<dim3(QKV_N / 32, HIDI / 32), dim3(32, 8)>>>(
        w_qkv, w1h, w1l, HIDI, QKV_N);

    // 2) QKV projection: [4096,2880] @ [2880,5120] + bias
    gemm_mma<128><<<dim3(QKV_N / 128, SEQ / 128), 256, SMEM1>>>(
        a1h, a1l, w1h, w1l, b_qkv, qkvb, SEQ, QKV_N, HIDI);

    // 3) YaRN RoPE in place (q scaled by D^-0.5)
    rope_kernel<<<dim3(SEQ, 9), dim3(32, 8)>>>(qkvb, pos);

    // 4) Sliding-window attention; writes bf16 hi/lo split directly
    attn_kernel<<<dim3(NKV, SEQ), 256>>>(qkvb, sinks, a2h, a2l);

    // 5) O-GEMM weight split
    transpose_split<<<dim3(HIDI / 32, ATT_N / 32), dim3(32, 8)>>>(
        w_o, w2h, w2l, ATT_N, HIDI);

    // 6) Output projection: [4096,4096] @ [4096,2880] + bias
    gemm_mma<96><<<dim3(HIDI / 96, SEQ / 128), 256, SMEM2>>>(
        a2h, a2l, w2h, w2l, b_o, outp, SEQ, HIDI, ATT_N);
}

// round 17
// speedup vs baseline: 2.1757x; 1.2106x over previous
#include <cuda_runtime.h>
#include <cuda_bf16.h>
#include <math.h>
#include <stdint.h>

#define SEQ   4096
#define HIDI  2880
#define NH    64
#define NKV   8
#define DH    64
#define QKV_N 5120          // (64 + 2*8) * 64
#define ATT_N 4096          // 64 * 64
#define TB    4             // tokens per attention CTA

// ---------------------------------------------------------------------------
// Scratch (allocation-free rule: __device__ globals)
// ---------------------------------------------------------------------------
__device__ float g_qkv [(size_t)SEQ * QKV_N];          // [S,5120] q|k|v rows
__device__ float g_invf[32];                           // YaRN inv_freq table
__device__ __nv_bfloat16 g_a1h[(size_t)SEQ * HIDI];    // hidden split
__device__ __nv_bfloat16 g_a1l[(size_t)SEQ * HIDI];
__device__ __nv_bfloat16 g_w1h[(size_t)QKV_N * HIDI];  // w_qkv^T split [N,K]
__device__ __nv_bfloat16 g_w1l[(size_t)QKV_N * HIDI];
__device__ __nv_bfloat16 g_a2h[(size_t)SEQ * ATT_N];   // attn-out split (fused)
__device__ __nv_bfloat16 g_a2l[(size_t)SEQ * ATT_N];
__device__ __nv_bfloat16 g_w2h[(size_t)HIDI * ATT_N];  // w_o^T split [N,K]
__device__ __nv_bfloat16 g_w2l[(size_t)HIDI * ATT_N];

// ---------------------------------------------------------------------------
// Portable (non-suffix-gated) PTX helpers: cp.async / ldmatrix / mma.sync
// ---------------------------------------------------------------------------
__device__ __forceinline__ uint32_t smem_to_u32(const void* p) {
    uint32_t a;
    asm("{ .reg .u64 t; cvta.to.shared.u64 t, %1; cvt.u32.u64 %0, t; }"
        : "=r"(a) : "l"(p));
    return a;
}
__device__ __forceinline__ void cp16(uint32_t saddr, const void* g) {
    asm volatile("cp.async.cg.shared.global [%0], [%1], 16;"
                 :: "r"(saddr), "l"(g) : "memory");
}
#define CP_COMMIT() asm volatile("cp.async.commit_group;" ::: "memory")
#define CP_WAIT0()  asm volatile("cp.async.wait_group 0;" ::: "memory")

#define LDSM4(r0, r1, r2, r3, addr) \
    asm volatile("ldmatrix.sync.aligned.m8n8.x4.shared.b16 {%0,%1,%2,%3}, [%4];" \
        : "=r"(r0), "=r"(r1), "=r"(r2), "=r"(r3) : "r"(addr))

#define MMA_BF16(d, a, b) \
    asm volatile("mma.sync.aligned.m16n8k16.row.col.f32.bf16.bf16.f32 " \
        "{%0,%1,%2,%3}, {%4,%5,%6,%7}, {%8,%9}, {%0,%1,%2,%3};" \
        : "+f"((d)[0]), "+f"((d)[1]), "+f"((d)[2]), "+f"((d)[3]) \
        : "r"((a)[0]), "r"((a)[1]), "r"((a)[2]), "r"((a)[3]), \
          "r"((b)[0]), "r"((b)[1]))

// ---------------------------------------------------------------------------
// YaRN inv_freq table init: 32 threads, fp64 once (negligible), fp32 result.
// ---------------------------------------------------------------------------
__global__ void yarn_init()
{
    int i = threadIdx.x;                              // 0..31
    const double LN_BASE = 11.918390573078392;        // ln(150000)
    double pf = exp((double)i * (LN_BASE / 32.0));
    double extrap = 1.0 / pf;
    double interp = extrap * (1.0 / 32.0);
    double ramp = ((double)i - 8.0) * 0.1;            // low=8, high=18
    ramp = fmin(fmax(ramp, 0.0), 1.0);
    g_invf[i] = (float)(interp * ramp + extrap * (1.0 - ramp));
}

// ---------------------------------------------------------------------------
// Elementwise split (vectorized): x -> bf16 hi + bf16 lo (lo = bf16(x - hi))
// ---------------------------------------------------------------------------
__global__ void split_rows(const float4* __restrict__ X,
                           __nv_bfloat162* __restrict__ hi,
                           __nv_bfloat162* __restrict__ lo, size_t n4)
{
    for (size_t i = (size_t)blockIdx.x * blockDim.x + threadIdx.x; i < n4;
         i += (size_t)gridDim.x * blockDim.x) {
        float4 v = X[i];
        __nv_bfloat16 hx = __float2bfloat16(v.x);
        __nv_bfloat16 hy = __float2bfloat16(v.y);
        __nv_bfloat16 hz = __float2bfloat16(v.z);
        __nv_bfloat16 hw = __float2bfloat16(v.w);
        hi[2 * i]     = __nv_bfloat162(hx, hy);
        hi[2 * i + 1] = __nv_bfloat162(hz, hw);
        lo[2 * i]     = __nv_bfloat162(
            __float2bfloat16(v.x - __bfloat162float(hx)),
            __float2bfloat16(v.y - __bfloat162float(hy)));
        lo[2 * i + 1] = __nv_bfloat162(
            __float2bfloat16(v.z - __bfloat162float(hz)),
            __float2bfloat16(v.w - __bfloat162float(hw)));
    }
}

// ---------------------------------------------------------------------------
// Transpose + split: W[K,N] (row-major) -> T[N,K] bf16 hi/lo
// ---------------------------------------------------------------------------
__global__ void transpose_split(const float* __restrict__ W,
                                __nv_bfloat16* __restrict__ Thi,
                                __nv_bfloat16* __restrict__ Tlo, int K, int N)
{
    __shared__ float t[32][33];
    const int n0 = blockIdx.x * 32, k0 = blockIdx.y * 32;
    const int tx = threadIdx.x, ty = threadIdx.y;     // 32 x 8
    #pragma unroll
    for (int i = 0; i < 32; i += 8)
        t[ty + i][tx] = W[(size_t)(k0 + ty + i) * N + n0 + tx];
    __syncthreads();
    #pragma unroll
    for (int i = 0; i < 32; i += 8) {
        float v = t[tx][ty + i];                      // = W[k0+tx][n0+ty+i]
        __nv_bfloat16 h = __float2bfloat16(v);
        size_t o = (size_t)(n0 + ty + i) * K + k0 + tx;
        Thi[o] = h;
        Tlo[o] = __float2bfloat16(v - __bfloat162float(h));
    }
}

// ---------------------------------------------------------------------------
// Stage loader for GEMM (see gemm_mma). Rows padded to 80B.
// ---------------------------------------------------------------------------
template <int BN>
__device__ __forceinline__ void stage_load(
    uint32_t st,
    const __nv_bfloat16* __restrict__ Ah, const __nv_bfloat16* __restrict__ Al,
    const __nv_bfloat16* __restrict__ Bh, const __nv_bfloat16* __restrict__ Bl,
    int row0, int col0, int K, int k0, int tid)
{
    constexpr int ABY = 128 * 80;
    constexpr int BBY = BN * 80;
    #pragma unroll
    for (int i = tid; i < 512; i += 256) {            // A: 128 rows x 4 chunks
        int r = i >> 2, c = i & 3;
        size_t go = (size_t)(row0 + r) * K + k0 + c * 8;
        uint32_t so = r * 80 + c * 16;
        cp16(st + so,       Ah + go);
        cp16(st + ABY + so, Al + go);
    }
    #pragma unroll
    for (int i = tid; i < BN * 4; i += 256) {         // B: BN rows x 4 chunks
        int r = i >> 2, c = i & 3;
        size_t go = (size_t)(col0 + r) * K + k0 + c * 8;
        uint32_t so = r * 80 + c * 16;
        cp16(st + 2 * ABY + so,       Bh + go);
        cp16(st + 2 * ABY + BBY + so, Bl + go);
    }
    CP_COMMIT();
}

// ---------------------------------------------------------------------------
// Split-bf16 GEMM via mma.sync.m16n8k16 (portable sm_80+ path).
// C[M,N] = A[M,K] @ B^T + bias, B stored [N,K] K-major.
// Products: Ah*Bh + Ah*Bl + Al*Bh, fp32 accum (dropped Al*Bl ~2^-18 rel).
// Block 256 thr = 8 warps (4 along M x 2 along N); BM=128, BN=128|96, BK=32.
// ---------------------------------------------------------------------------
template <int BN>
__global__ __launch_bounds__(256, 1) void gemm_mma(
    const __nv_bfloat16* __restrict__ Ah, const __nv_bfloat16* __restrict__ Al,
    const __nv_bfloat16* __restrict__ Bh, const __nv_bfloat16* __restrict__ Bl,
    const float* __restrict__ bias, float* __restrict__ C,
    int M, int N, int K)
{
    extern __shared__ char smem[];
    constexpr int ABY   = 128 * 80;
    constexpr int BBY   = BN * 80;
    constexpr int STAGE = 2 * ABY + 2 * BBY;
    constexpr int WN    = BN / 2;                     // warp N extent
    constexpr int NT    = WN / 8;                     // n-tiles per warp

    const int tid = threadIdx.x, lane = tid & 31, wid = tid >> 5;
    const int wm = wid & 3, wn = wid >> 2;            // 4 x 2 warp grid
    const int row0 = blockIdx.y * 128, col0 = blockIdx.x * BN;
    const uint32_t sb = smem_to_u32(smem);

    float acc[2][NT][4];
    #pragma unroll
    for (int mi = 0; mi < 2; mi++)
        #pragma unroll
        for (int ni = 0; ni < NT; ni++)
            #pragma unroll
            for (int k = 0; k < 4; k++) acc[mi][ni][k] = 0.f;

    const int rA  = lane & 15;
    const int cAb = (lane >> 4) * 16;
    const int rB  = (lane & 7) + ((lane >> 4) << 3);
    const int cBb = ((lane >> 3) & 1) * 16;

    const int nch = K / 32;
    stage_load<BN>(sb, Ah, Al, Bh, Bl, row0, col0, K, 0, tid);

    for (int ch = 0; ch < nch; ++ch) {
        CP_WAIT0();
        __syncthreads();
        if (ch + 1 < nch)
            stage_load<BN>(sb + ((ch + 1) & 1) * STAGE,
                           Ah, Al, Bh, Bl, row0, col0, K, (ch + 1) * 32, tid);
        const uint32_t st = sb + (ch & 1) * STAGE;

        #pragma unroll
        for (int ks = 0; ks < 2; ks++) {
            uint32_t ah[2][4], al[2][4], bh[NT][2], bl[NT][2];
            #pragma unroll
            for (int mi = 0; mi < 2; mi++) {
                uint32_t a = st + (wm * 32 + mi * 16 + rA) * 80 + ks * 32 + cAb;
                LDSM4(ah[mi][0], ah[mi][1], ah[mi][2], ah[mi][3], a);
                LDSM4(al[mi][0], al[mi][1], al[mi][2], al[mi][3], a + ABY);
            }
            #pragma unroll
            for (int j = 0; j < NT / 2; j++) {        // each x4 = 2 n-tiles
                uint32_t a = st + 2 * ABY + (wn * WN + j * 16 + rB) * 80
                           + ks * 32 + cBb;
                LDSM4(bh[2*j][0], bh[2*j][1], bh[2*j+1][0], bh[2*j+1][1], a);
                LDSM4(bl[2*j][0], bl[2*j][1], bl[2*j+1][0], bl[2*j+1][1], a + BBY);
            }
            #pragma unroll
            for (int ni = 0; ni < NT; ni++)
                #pragma unroll
                for (int mi = 0; mi < 2; mi++) {
                    MMA_BF16(acc[mi][ni], ah[mi], bh[ni]);
                    MMA_BF16(acc[mi][ni], ah[mi], bl[ni]);
                    MMA_BF16(acc[mi][ni], al[mi], bh[ni]);
                }
        }
    }

    // epilogue: c0,c1 = (row lane/4, col 2(lane%4)+{0,1}); c2,c3 = row+8
    const int rb = row0 + wm * 32 + (lane >> 2);
    const int cb = col0 + wn * WN + (lane & 3) * 2;
    #pragma unroll
    for (int mi = 0; mi < 2; mi++)
        #pragma unroll
        for (int ni = 0; ni < NT; ni++) {
            int c = cb + ni * 8;
            float2 bz = *reinterpret_cast<const float2*>(bias + c);
            int r = rb + mi * 16;
            float2 v0 = make_float2(acc[mi][ni][0] + bz.x, acc[mi][ni][1] + bz.y);
            float2 v1 = make_float2(acc[mi][ni][2] + bz.x, acc[mi][ni][3] + bz.y);
            *reinterpret_cast<float2*>(C + (size_t)r * N + c)       = v0;
            *reinterpret_cast<float2*>(C + (size_t)(r + 8) * N + c) = v1;
        }
}

// ---------------------------------------------------------------------------
// YaRN RoPE, in place on g_qkv (pure fp32; inv_freq from g_invf table).
// ---------------------------------------------------------------------------
__global__ void rope_kernel(float* __restrict__ qkv, const int* __restrict__ pos)
{
    const int h = blockIdx.y * blockDim.y + threadIdx.y;  // 0..71
    if (h >= NH + NKV) return;
    const int t = blockIdx.x;
    const int i = threadIdx.x;                            // 0..31 freq index

    float fr = (float)pos[t] * g_invf[i];
    float s, c;
    sincosf(fr, &s, &c);
    const float mscale = 1.3465735902799727f;             // 0.1*ln(32)+1
    c *= mscale; s *= mscale;

    const float scale = (h < NH) ? 0.125f : 1.0f;         // D^-0.5 for q only
    float* base = qkv + (size_t)t * QKV_N + h * 64;
    float x1 = base[i];
    float x2 = base[i + 32];
    base[i]      = (x1 * c - x2 * s) * scale;
    base[i + 32] = (x2 * c + x1 * s) * scale;
}

// ---------------------------------------------------------------------------
// Sliding-window attention with sinks, TB=4 tokens per CTA.
// Block = (kv-head kk, token-tile p0/TB). One union K/V window
// [ks_u = max(0,p0-127), p0+TB-1] (NR <= 131 rows) serves all TB tokens.
// 8 warps; warp w = q-head w of the group, iterating ti=0..TB-1.
// Key slot j in [0,128) of token p maps to smem row (p-127-ks_u)+j;
// valid <=> row >= 0 (delta = 127-j in [0,128) automatically).
// Two-phase smem reuse (K pass then V pass). Epilogue writes bf16 hi/lo
// split directly (fused O-GEMM input prep).
// smem: KV 132*68 | qs 32*64 | sc 32*128  (60480 B dynamic)
// ---------------------------------------------------------------------------
#define ATTN_SMEM ((132 * 68 + 32 * 64 + 32 * 128) * 4)
__global__ __launch_bounds__(256) void attn_kernel(
    const float* __restrict__ qkv, const float* __restrict__ sinks,
    __nv_bfloat16* __restrict__ oh, __nv_bfloat16* __restrict__ ol)
{
    extern __shared__ float sm[];
    float* KV = sm;                    // 132 rows x 68 stride
    float* qs = sm + 132 * 68;         // 32 pairs x 64
    float* sc = qs + 32 * 64;          // 32 pairs x 128

    const int p0   = blockIdx.y * TB;
    const int kk   = blockIdx.x;
    const int tid  = threadIdx.x;
    const int lane = tid & 31;
    const int w    = tid >> 5;                        // q-head within group
    const int ks_u = max(0, p0 - 127);
    const int NR   = p0 + TB - ks_u;                  // rows in union window

    // ---- load K union window ----
    const float* kbase = qkv + (size_t)ks_u * QKV_N + ATT_N + kk * 64;
    for (int idx = tid; idx < 132 * 16; idx += 256) {
        int j = idx >> 4, f = idx & 15;
        if (j < NR)
            *reinterpret_cast<float4*>(&KV[j * 68 + f * 4]) =
                *reinterpret_cast<const float4*>(kbase + (size_t)j * QKV_N + f * 4);
    }
    // ---- load q for TB tokens x 8 heads (pair = ti*8 + g) ----
    for (int idx = tid; idx < 32 * 16; idx += 256) {
        int pr = idx >> 4, f = idx & 15;
        int ti = pr >> 3, g = pr & 7;
        *reinterpret_cast<float4*>(&qs[pr * 64 + f * 4]) =
            *reinterpret_cast<const float4*>(
                qkv + (size_t)(p0 + ti) * QKV_N + (kk * 8 + g) * 64 + f * 4);
    }
    __syncthreads();

    // ---- scores + softmax per (ti, head w) ----
    const float sink = sinks[kk * 8 + w];
    float inv_d[TB];
    #pragma unroll
    for (int ti = 0; ti < TB; ti++) {
        const int base = p0 + ti - 127 - ks_u;        // smem row of key slot 0
        const float4* qv = reinterpret_cast<const float4*>(qs + (ti * 8 + w) * 64);
        float sv[4];
        #pragma unroll
        for (int jj = 0; jj < 4; jj++) {
            int j = lane + jj * 32;                   // key slot 0..127
            int row = base + j;
            float s = -3.0e38f;
            if (row >= 0) {
                const float4* kv = reinterpret_cast<const float4*>(KV + row * 68);
                float a = 0.f;
                #pragma unroll
                for (int f = 0; f < 16; f++) {
                    float4 kq = kv[f];
                    float4 qq = qv[f];
                    a += kq.x * qq.x + kq.y * qq.y + kq.z * qq.z + kq.w * qq.w;
                }
                s = a;
            }
            sv[jj] = s;
        }
        float m = fmaxf(fmaxf(sv[0], sv[1]), fmaxf(sv[2], sv[3]));
        #pragma unroll
        for (int o = 16; o > 0; o >>= 1)
            m = fmaxf(m, __shfl_xor_sync(0xffffffffu, m, o));
        m = fmaxf(m, sink);
        float sum = 0.f;
        #pragma unroll
        for (int jj = 0; jj < 4; jj++) {
            float e = expf(sv[jj] - m);               // invalid slots -> 0
            sum += e;
            sc[(ti * 8 + w) * 128 + lane + jj * 32] = e;
        }
        #pragma unroll
        for (int o = 16; o > 0; o >>= 1)
            sum += __shfl_xor_sync(0xffffffffu, sum, o);
        inv_d[ti] = 1.0f / (sum + expf(sink - m));
    }
    __syncthreads();                                  // all warps done with K

    // ---- reload buffer with V ----
    const float* vbase = qkv + (size_t)ks_u * QKV_N + ATT_N + NKV * 64 + kk * 64;
    for (int idx = tid; idx < 132 * 16; idx += 256) {
        int j = idx >> 4, f = idx & 15;
        if (j < NR)
            *reinterpret_cast<float4*>(&KV[j * 68 + f * 4]) =
                *reinterpret_cast<const float4*>(vbase + (size_t)j * QKV_N + f * 4);
    }
    __syncthreads();

    // ---- P @ V per ti : lane handles dims lane, lane+32 ----
    #pragma unroll
    for (int ti = 0; ti < TB; ti++) {
        const int base = p0 + ti - 127 - ks_u;
        const float* sp = sc + (ti * 8 + w) * 128;
        float acc0 = 0.f, acc1 = 0.f;
        for (int j = max(0, -base); j < 128; j++) {
            float pw = sp[j];
            int row = base + j;
            acc0 += pw * KV[row * 68 + lane];
            acc1 += pw * KV[row * 68 + 32 + lane];
        }
        const size_t o = (size_t)(p0 + ti) * ATT_N + (kk * 8 + w) * 64 + lane;
        float v0 = acc0 * inv_d[ti];
        float v1 = acc1 * inv_d[ti];
        __nv_bfloat16 h0 = __float2bfloat16(v0);
        __nv_bfloat16 h1 = __float2bfloat16(v1);
        oh[o]      = h0;
        oh[o + 32] = h1;
        ol[o]      = __float2bfloat16(v0 - __bfloat162float(h0));
        ol[o + 32] = __float2bfloat16(v1 - __bfloat162float(h1));
    }
}

// ---------------------------------------------------------------------------
extern "C" void kernel_launch(void* const* d_in, const int* in_sizes, int n_in,
                              void* d_out, int out_size)
{
    const float* hidden = (const float*)d_in[0];
    const int*   pos    = (const int*)  d_in[1];
    const float* w_qkv  = (const float*)d_in[2];
    const float* b_qkv  = (const float*)d_in[3];
    const float* w_o    = (const float*)d_in[4];
    const float* b_o    = (const float*)d_in[5];
    const float* sinks  = (const float*)d_in[6];
    float* outp = (float*)d_out;

    void* p;
    cudaGetSymbolAddress(&p, g_qkv);  float* qkvb  = (float*)p;
    cudaGetSymbolAddress(&p, g_a1h);  __nv_bfloat16* a1h = (__nv_bfloat16*)p;
    cudaGetSymbolAddress(&p, g_a1l);  __nv_bfloat16* a1l = (__nv_bfloat16*)p;
    cudaGetSymbolAddress(&p, g_w1h);  __nv_bfloat16* w1h = (__nv_bfloat16*)p;
    cudaGetSymbolAddress(&p, g_w1l);  __nv_bfloat16* w1l = (__nv_bfloat16*)p;
    cudaGetSymbolAddress(&p, g_a2h);  __nv_bfloat16* a2h = (__nv_bfloat16*)p;
    cudaGetSymbolAddress(&p, g_a2l);  __nv_bfloat16* a2l = (__nv_bfloat16*)p;
    cudaGetSymbolAddress(&p, g_w2h);  __nv_bfloat16* w2h = (__nv_bfloat16*)p;
    cudaGetSymbolAddress(&p, g_w2l);  __nv_bfloat16* w2l = (__nv_bfloat16*)p;

    // dynamic smem: 2 stages x (2*128*80 + 2*BN*80)
    constexpr int SMEM1 = 2 * (2 * 128 * 80 + 2 * 128 * 80);  // 81920 (BN=128)
    constexpr int SMEM2 = 2 * (2 * 128 * 80 + 2 * 96 * 80);   // 71680 (BN=96)
    cudaFuncSetAttribute(gemm_mma<128>,
                         cudaFuncAttributeMaxDynamicSharedMemorySize, SMEM1);
    cudaFuncSetAttribute(gemm_mma<96>,
                         cudaFuncAttributeMaxDynamicSharedMemorySize, SMEM2);
    cudaFuncSetAttribute(attn_kernel,
                         cudaFuncAttributeMaxDynamicSharedMemorySize, ATTN_SMEM);

    // 0) YaRN inv_freq table (fp64 once, 32 threads)
    yarn_init<<<1, 32>>>();

    // 1) split inputs of QKV GEMM
    split_rows<<<2048, 256>>>((const float4*)hidden, (__nv_bfloat162*)a1h,
                              (__nv_bfloat162*)a1l, (size_t)SEQ * HIDI / 4);
    transpose_split<<<dim3(QKV_N / 32, HIDI / 32), dim3(32, 8)>>>(
        w_qkv, w1h, w1l, HIDI, QKV_N);

    // 2) QKV projection: [4096,2880] @ [2880,5120] + bias
    gemm_mma<128><<<dim3(QKV_N / 128, SEQ / 128), 256, SMEM1>>>(
        a1h, a1l, w1h, w1l, b_qkv, qkvb, SEQ, QKV_N, HIDI);

    // 3) YaRN RoPE in place (fp32; q scaled by D^-0.5)
    rope_kernel<<<dim3(SEQ, 9), dim3(32, 8)>>>(qkvb, pos);

    // 4) Sliding-window attention, TB tokens/CTA; writes bf16 hi/lo split
    attn_kernel<<<dim3(NKV, SEQ / TB), 256, ATTN_SMEM>>>(qkvb, sinks, a2h, a2l);

    // 5) O-GEMM weight split
    transpose_split<<<dim3(HIDI / 32, ATT_N / 32), dim3(32, 8)>>>(
        w_o, w2h, w2l, ATT_N, HIDI);

    // 6) Output projection: [4096,4096] @ [4096,2880] + bias
    gemm_mma<96><<<dim3(HIDI / 96, SEQ / 128), 256, SMEM2>>>(
        a2h, a2l, w2h, w2l, b_o, outp, SEQ, HIDI, ATT_N);
}